// round 3
// baseline (speedup 1.0000x reference)
#include <cuda_runtime.h>
#include <cstdint>

#define W_DIM 81920
#define N_DIM 4
#define C_DIM 64
#define O_DIM 64
#define K_DIM 10
#define CK    640            // C*K, contraction length
#define PITCH 644            // padded row pitch (floats): 644 % 32 == 4 -> conflict-free float4 phases
#define TILE_W 16
#define TILES_PER_N (W_DIM / TILE_W)          // 5120
#define NTILES      (N_DIM * TILES_PER_N)     // 20480
#define TBL_ELEMS   (W_DIM * K_DIM)           // 819200

// smem: weight 64*644 floats + gather 16*644 floats + 160 idx ints
#define SMEM_FLOATS (O_DIM * PITCH + TILE_W * PITCH)
#define SMEM_BYTES  (SMEM_FLOATS * 4 + TILE_W * K_DIM * 4)   // 206720

// Scratch (static device globals -- no runtime allocation)
__device__ float g_xT[(size_t)N_DIM * W_DIM * C_DIM];  // input transposed to [N,W,C]
__device__ float g_wT[O_DIM * CK];                     // weight rearranged to [O][k*64+c]
__device__ int   g_idx[TBL_ELEMS];                     // canonical int32 gather table
__device__ int   g_is_i32;                             // 1 if conv_table buffer is int32

// ---------------------------------------------------------------------------
// Detect conv_table dtype. Genuine int64 (values < 2^31) => every odd 32-bit
// word is 0. int32 data => odd words are random indices; 64 consecutive zeros
// is impossible. Probe reads only the first 512 bytes (safe either way).
// ---------------------------------------------------------------------------
__global__ void detect_kernel(const int* __restrict__ t32) {
    __shared__ int f;
    if (threadIdx.x == 0) f = 0;
    __syncthreads();
    if (t32[2 * threadIdx.x + 1] != 0) atomicOr(&f, 1);
    __syncthreads();
    if (threadIdx.x == 0) g_is_i32 = f;
}

// Canonicalize table into g_idx (int32), whichever dtype it is.
__global__ void convert_kernel(const int* __restrict__ t32) {
    int i = blockIdx.x * 256 + threadIdx.x;
    if (i < TBL_ELEMS)
        g_idx[i] = g_is_i32 ? t32[i] : t32[2 * i];   // low word of int64
}

// ---------------------------------------------------------------------------
// input [N,C,W] -> g_xT [N,W,C]
// ---------------------------------------------------------------------------
__global__ void transpose_kernel(const float* __restrict__ in) {
    __shared__ float t[32][33];
    int n  = blockIdx.z;
    int c0 = blockIdx.y << 5;
    int w0 = blockIdx.x << 5;
    int tx = threadIdx.x, ty = threadIdx.y;

    const size_t inb = ((size_t)n * C_DIM + c0) * W_DIM + w0;
#pragma unroll
    for (int i = 0; i < 32; i += 8)
        t[ty + i][tx] = in[inb + (size_t)(ty + i) * W_DIM + tx];
    __syncthreads();
    const size_t ob = ((size_t)n * W_DIM + w0) * C_DIM + c0;
#pragma unroll
    for (int i = 0; i < 32; i += 8)
        g_xT[ob + (size_t)(ty + i) * C_DIM + tx] = t[tx][ty + i];
}

// ---------------------------------------------------------------------------
// weight [O,C,K,1] -> g_wT [O][k*64+c]
// ---------------------------------------------------------------------------
__global__ void wprep_kernel(const float* __restrict__ w) {
    int i = blockIdx.x * 256 + threadIdx.x;
    if (i < O_DIM * C_DIM * K_DIM) {
        int o = i / CK;
        int r = i - o * CK;
        int c = r / K_DIM;
        int k = r - c * K_DIM;
        g_wT[o * CK + k * C_DIM + c] = w[i];
    }
}

// ---------------------------------------------------------------------------
// Persistent main kernel: 1 CTA/SM, weight resident in smem,
// loop over 16-w tiles; f32x2 packed FMA inner loop.
// ---------------------------------------------------------------------------
__global__ void __launch_bounds__(256, 1)
conv_kernel(const float* __restrict__ bias,
            float* __restrict__ out) {
    extern __shared__ float smem[];
    float* s_w   = smem;                         // [64][644]
    float* s_g   = smem + O_DIM * PITCH;         // [16][644]
    int*   s_idx = (int*)(s_g + TILE_W * PITCH); // [160]

    const int tid  = threadIdx.x;
    const int warp = tid >> 5;
    const int lane = tid & 31;
    const int wq   = lane & 7;       // w in {wq, wq+8}
    const int oq   = lane >> 3;      // 0..3
    const int o0   = warp * 8 + oq * 2;
    const int o1   = o0 + 1;

    // Load weights into smem once (padded rows)
    for (int i = tid; i < O_DIM * (CK / 4); i += 256) {
        int o  = i / (CK / 4);
        int j4 = i - o * (CK / 4);
        reinterpret_cast<float4*>(s_w + o * PITCH)[j4] =
            reinterpret_cast<const float4*>(g_wT + o * CK)[j4];
    }
    const float b0 = bias[o0];
    const float b1 = bias[o1];
    __syncthreads();

    for (int t = blockIdx.x; t < NTILES; t += gridDim.x) {
        const int n  = t / TILES_PER_N;
        const int w0 = (t - n * TILES_PER_N) * TILE_W;

        // ---- load the 160 gather indices for this tile ----
        if (tid < TILE_W * K_DIM)
            s_idx[tid] = g_idx[w0 * K_DIM + tid];
        __syncthreads();

        // ---- gather 16*640 floats from transposed input ----
        const float* xTn = g_xT + (size_t)n * W_DIM * C_DIM;
#pragma unroll
        for (int i = 0; i < 10; ++i) {
            int lin = tid + 256 * i;       // 0..2559
            int row = lin >> 4;            // 0..159  == w*10 + k
            int c4  = (lin & 15) << 2;
            float4 v = *reinterpret_cast<const float4*>(
                xTn + (size_t)s_idx[row] * C_DIM + c4);
            int w = row / K_DIM;
            int k = row - w * K_DIM;
            *reinterpret_cast<float4*>(s_g + w * PITCH + k * C_DIM + c4) = v;
        }
        __syncthreads();

        // ---- compute: 2w x 2o register tile, f32x2 packed FMA ----
        const ulonglong2* gp0 = reinterpret_cast<const ulonglong2*>(s_g + wq * PITCH);
        const ulonglong2* gp1 = reinterpret_cast<const ulonglong2*>(s_g + (wq + 8) * PITCH);
        const ulonglong2* wp0 = reinterpret_cast<const ulonglong2*>(s_w + o0 * PITCH);
        const ulonglong2* wp1 = reinterpret_cast<const ulonglong2*>(s_w + o1 * PITCH);

        unsigned long long a00 = 0ull, a01 = 0ull, a10 = 0ull, a11 = 0ull;
#pragma unroll 4
        for (int j4 = 0; j4 < CK / 4; ++j4) {
            ulonglong2 ga = gp0[j4];
            ulonglong2 gb = gp1[j4];
            ulonglong2 wa = wp0[j4];
            ulonglong2 wb = wp1[j4];
            asm("fma.rn.f32x2 %0, %1, %2, %0;" : "+l"(a00) : "l"(ga.x), "l"(wa.x));
            asm("fma.rn.f32x2 %0, %1, %2, %0;" : "+l"(a01) : "l"(ga.x), "l"(wb.x));
            asm("fma.rn.f32x2 %0, %1, %2, %0;" : "+l"(a10) : "l"(gb.x), "l"(wa.x));
            asm("fma.rn.f32x2 %0, %1, %2, %0;" : "+l"(a11) : "l"(gb.x), "l"(wb.x));
            asm("fma.rn.f32x2 %0, %1, %2, %0;" : "+l"(a00) : "l"(ga.y), "l"(wa.y));
            asm("fma.rn.f32x2 %0, %1, %2, %0;" : "+l"(a01) : "l"(ga.y), "l"(wb.y));
            asm("fma.rn.f32x2 %0, %1, %2, %0;" : "+l"(a10) : "l"(gb.y), "l"(wa.y));
            asm("fma.rn.f32x2 %0, %1, %2, %0;" : "+l"(a11) : "l"(gb.y), "l"(wb.y));
        }

        // reduce packed halves, add bias, relu, store
        auto red = [](unsigned long long v) {
            return __uint_as_float((unsigned)v) + __uint_as_float((unsigned)(v >> 32));
        };
        float r00 = fmaxf(red(a00) + b0, 0.0f);  // (w=wq,   o=o0)
        float r01 = fmaxf(red(a01) + b1, 0.0f);  // (w=wq,   o=o1)
        float r10 = fmaxf(red(a10) + b0, 0.0f);  // (w=wq+8, o=o0)
        float r11 = fmaxf(red(a11) + b1, 0.0f);  // (w=wq+8, o=o1)

        const size_t ob = (size_t)n * O_DIM * W_DIM + w0;
        out[ob + (size_t)o0 * W_DIM + wq]     = r00;
        out[ob + (size_t)o0 * W_DIM + wq + 8] = r10;
        out[ob + (size_t)o1 * W_DIM + wq]     = r01;
        out[ob + (size_t)o1 * W_DIM + wq + 8] = r11;

        __syncthreads();   // protect s_g / s_idx before next tile's gather
    }
}

// ---------------------------------------------------------------------------
extern "C" void kernel_launch(void* const* d_in, const int* in_sizes, int n_in,
                              void* d_out, int out_size) {
    const float* input  = (const float*)d_in[0];
    const int*   tbl32  = (const int*)d_in[1];    // int32 OR int64 bits; detected on device
    const float* weight = (const float*)d_in[2];
    const float* bias   = (const float*)d_in[3];
    float*       out    = (float*)d_out;

    cudaFuncSetAttribute(conv_kernel,
                         cudaFuncAttributeMaxDynamicSharedMemorySize, SMEM_BYTES);

    int dev = 0;
    cudaGetDevice(&dev);
    int nsm = 148;
    cudaDeviceGetAttribute(&nsm, cudaDevAttrMultiProcessorCount, dev);

    detect_kernel<<<1, 64>>>(tbl32);
    convert_kernel<<<(TBL_ELEMS + 255) / 256, 256>>>(tbl32);
    transpose_kernel<<<dim3(W_DIM / 32, C_DIM / 32, N_DIM), dim3(32, 8)>>>(input);
    wprep_kernel<<<(O_DIM * C_DIM * K_DIM + 255) / 256, 256>>>(weight);
    conv_kernel<<<nsm, 256, SMEM_BYTES>>>(bias, out);
}

// round 4
// speedup vs baseline: 1.1191x; 1.1191x over previous
#include <cuda_runtime.h>
#include <cstdint>

#define W_DIM 81920
#define N_DIM 4
#define C_DIM 64
#define O_DIM 64
#define K_DIM 10
#define CK    640                              // C*K contraction length
#define NJ4   (CK / 4)                         // 160 j4 steps
#define TILE_W 16
#define TILES_PER_N (W_DIM / TILE_W)           // 5120
#define NTILES      (N_DIM * TILES_PER_N)      // 20480
#define TBL_ELEMS   (W_DIM * K_DIM)            // 819200

// smem: weight [160][64] float4 + gather [160][16] float4  (no padding needed)
#define SW_F4   (NJ4 * O_DIM)                  // 10240 float4 = 163840 B
#define SG_F4   (NJ4 * TILE_W)                 // 2560 float4  =  40960 B
#define SMEM_BYTES ((SW_F4 + SG_F4) * 16)      // 204800 B

// Scratch (static device globals -- no runtime allocation)
__device__ float g_xT[(size_t)N_DIM * W_DIM * C_DIM];  // input transposed [N,W,C]
__device__ float g_wT[O_DIM * CK];                     // weight, j4-interleaved [j4][o][4]
__device__ int   g_idx[TBL_ELEMS];                     // canonical int32 gather table
__device__ int   g_is_i32;

// ---------------------------------------------------------------------------
// conv_table dtype detection (int64 per reference, but JAX x64-off => int32).
// Genuine int64 < 2^31 => every odd 32-bit word is 0. Probe first 512 B.
// ---------------------------------------------------------------------------
__global__ void detect_kernel(const int* __restrict__ t32) {
    __shared__ int f;
    if (threadIdx.x == 0) f = 0;
    __syncthreads();
    if (t32[2 * threadIdx.x + 1] != 0) atomicOr(&f, 1);
    __syncthreads();
    if (threadIdx.x == 0) g_is_i32 = f;
}

__global__ void convert_kernel(const int* __restrict__ t32) {
    int i = blockIdx.x * 256 + threadIdx.x;
    if (i < TBL_ELEMS)
        g_idx[i] = g_is_i32 ? t32[i] : t32[2 * i];   // low word of int64
}

// ---------------------------------------------------------------------------
// input [N,C,W] -> g_xT [N,W,C]
// ---------------------------------------------------------------------------
__global__ void transpose_kernel(const float* __restrict__ in) {
    __shared__ float t[32][33];
    int n  = blockIdx.z;
    int c0 = blockIdx.y << 5;
    int w0 = blockIdx.x << 5;
    int tx = threadIdx.x, ty = threadIdx.y;

    const size_t inb = ((size_t)n * C_DIM + c0) * W_DIM + w0;
#pragma unroll
    for (int i = 0; i < 32; i += 8)
        t[ty + i][tx] = in[inb + (size_t)(ty + i) * W_DIM + tx];
    __syncthreads();
    const size_t ob = ((size_t)n * W_DIM + w0) * C_DIM + c0;
#pragma unroll
    for (int i = 0; i < 32; i += 8)
        g_xT[ob + (size_t)(ty + i) * C_DIM + tx] = t[tx][ty + i];
}

// ---------------------------------------------------------------------------
// weight [O,C,K,1] -> g_wT j4-interleaved: dst[(j4*64 + o)*4 + e], j = k*64+c
// ---------------------------------------------------------------------------
__global__ void wprep_kernel(const float* __restrict__ w) {
    int i = blockIdx.x * 256 + threadIdx.x;
    if (i < O_DIM * C_DIM * K_DIM) {
        int o = i / CK;
        int r = i - o * CK;
        int c = r / K_DIM;
        int k = r - c * K_DIM;
        int j = k * C_DIM + c;
        g_wT[((j >> 2) * O_DIM + o) * 4 + (j & 3)] = w[i];
    }
}

// ---------------------------------------------------------------------------
// Persistent conv kernel: 1 CTA/SM, weights resident in smem (j4-major),
// register-prefetched gather pipeline, f32x2 packed-FMA inner loop.
// ---------------------------------------------------------------------------
__global__ void __launch_bounds__(256, 1)
conv_kernel(const float* __restrict__ bias,
            float* __restrict__ out) {
    extern __shared__ float smem[];
    float4* s_w = reinterpret_cast<float4*>(smem);          // [160][64]
    float4* s_g = reinterpret_cast<float4*>(smem) + SW_F4;  // [160][16]

    const int tid  = threadIdx.x;
    const int warp = tid >> 5;
    const int lane = tid & 31;
    const int wq   = lane & 7;        // compute: w rows {wq, wq+8}
    const int oq   = lane >> 3;       // 0..3
    const int o0   = warp * 8 + oq * 2;
    const int o1   = o0 + 1;
    const int gw   = tid & 15;        // gather: w row
    const int cc   = tid >> 4;        // gather: channel chunk (c = cc*4..+3)

    // Weights into smem once
    for (int i = tid; i < SW_F4; i += 256)
        s_w[i] = reinterpret_cast<const float4*>(g_wT)[i];
    const float b0 = bias[o0];
    const float b1 = bias[o1];

    // ---- prologue: prefetch first tile's gather into registers ----
    int t = blockIdx.x;
    float4 v[10];
    {
        int n  = t / TILES_PER_N;
        int w0 = (t - n * TILES_PER_N) * TILE_W;
        const float* xTn = g_xT + (size_t)n * W_DIM * C_DIM;
        int idxr[10];
#pragma unroll
        for (int i = 0; i < 10; ++i) idxr[i] = g_idx[(w0 + gw) * K_DIM + i];
#pragma unroll
        for (int i = 0; i < 10; ++i)
            v[i] = *reinterpret_cast<const float4*>(
                xTn + (size_t)idxr[i] * C_DIM + cc * 4);
    }
    __syncthreads();   // weights ready

    for (; t < NTILES; t += gridDim.x) {
        const int n_cur  = t / TILES_PER_N;
        const int w0_cur = (t - n_cur * TILES_PER_N) * TILE_W;

        // ---- store prefetched gather (fully coalesced, conflict-free) ----
#pragma unroll
        for (int i = 0; i < 10; ++i)
            s_g[i * 256 + tid] = v[i];   // float4 index = (k*16+cc)*16 + w
        __syncthreads();

        // ---- prefetch NEXT tile's gather (overlaps compute below) ----
        {
            int t2 = t + gridDim.x;
            if (t2 >= NTILES) t2 = NTILES - 1;   // safe, deterministic
            int n2  = t2 / TILES_PER_N;
            int w02 = (t2 - n2 * TILES_PER_N) * TILE_W;
            const float* xTn = g_xT + (size_t)n2 * W_DIM * C_DIM;
            int idxr[10];
#pragma unroll
            for (int i = 0; i < 10; ++i) idxr[i] = g_idx[(w02 + gw) * K_DIM + i];
#pragma unroll
            for (int i = 0; i < 10; ++i)
                v[i] = *reinterpret_cast<const float4*>(
                    xTn + (size_t)idxr[i] * C_DIM + cc * 4);
        }

        // ---- compute: 2w x 2o register tile, f32x2 packed FMA ----
        const ulonglong2* gp = reinterpret_cast<const ulonglong2*>(s_g);
        const ulonglong2* wp = reinterpret_cast<const ulonglong2*>(s_w);

        unsigned long long a00 = 0ull, a01 = 0ull, a10 = 0ull, a11 = 0ull;
#pragma unroll 4
        for (int j4 = 0; j4 < NJ4; ++j4) {
            ulonglong2 ga = gp[j4 * 16 + wq];
            ulonglong2 gb = gp[j4 * 16 + wq + 8];
            ulonglong2 wa = wp[j4 * 64 + o0];
            ulonglong2 wb = wp[j4 * 64 + o1];
            asm("fma.rn.f32x2 %0, %1, %2, %0;" : "+l"(a00) : "l"(ga.x), "l"(wa.x));
            asm("fma.rn.f32x2 %0, %1, %2, %0;" : "+l"(a01) : "l"(ga.x), "l"(wb.x));
            asm("fma.rn.f32x2 %0, %1, %2, %0;" : "+l"(a10) : "l"(gb.x), "l"(wa.x));
            asm("fma.rn.f32x2 %0, %1, %2, %0;" : "+l"(a11) : "l"(gb.x), "l"(wb.x));
            asm("fma.rn.f32x2 %0, %1, %2, %0;" : "+l"(a00) : "l"(ga.y), "l"(wa.y));
            asm("fma.rn.f32x2 %0, %1, %2, %0;" : "+l"(a01) : "l"(ga.y), "l"(wb.y));
            asm("fma.rn.f32x2 %0, %1, %2, %0;" : "+l"(a10) : "l"(gb.y), "l"(wa.y));
            asm("fma.rn.f32x2 %0, %1, %2, %0;" : "+l"(a11) : "l"(gb.y), "l"(wb.y));
        }

        // reduce packed halves, add bias, relu, store
        auto red = [](unsigned long long x) {
            return __uint_as_float((unsigned)x) + __uint_as_float((unsigned)(x >> 32));
        };
        float r00 = fmaxf(red(a00) + b0, 0.0f);
        float r01 = fmaxf(red(a01) + b1, 0.0f);
        float r10 = fmaxf(red(a10) + b0, 0.0f);
        float r11 = fmaxf(red(a11) + b1, 0.0f);

        const size_t ob = (size_t)n_cur * O_DIM * W_DIM + w0_cur;
        out[ob + (size_t)o0 * W_DIM + wq]     = r00;
        out[ob + (size_t)o0 * W_DIM + wq + 8] = r10;
        out[ob + (size_t)o1 * W_DIM + wq]     = r01;
        out[ob + (size_t)o1 * W_DIM + wq + 8] = r11;

        __syncthreads();   // s_g free for next tile's STS
    }
}

// ---------------------------------------------------------------------------
extern "C" void kernel_launch(void* const* d_in, const int* in_sizes, int n_in,
                              void* d_out, int out_size) {
    const float* input  = (const float*)d_in[0];
    const int*   tbl32  = (const int*)d_in[1];    // int32 or int64 bits; device-detected
    const float* weight = (const float*)d_in[2];
    const float* bias   = (const float*)d_in[3];
    float*       out    = (float*)d_out;

    cudaFuncSetAttribute(conv_kernel,
                         cudaFuncAttributeMaxDynamicSharedMemorySize, SMEM_BYTES);

    int dev = 0;
    cudaGetDevice(&dev);
    int nsm = 148;
    cudaDeviceGetAttribute(&nsm, cudaDevAttrMultiProcessorCount, dev);

    detect_kernel<<<1, 64>>>(tbl32);
    convert_kernel<<<(TBL_ELEMS + 255) / 256, 256>>>(tbl32);
    transpose_kernel<<<dim3(W_DIM / 32, C_DIM / 32, N_DIM), dim3(32, 8)>>>(input);
    wprep_kernel<<<(O_DIM * C_DIM * K_DIM + 255) / 256, 256>>>(weight);
    conv_kernel<<<nsm, 256, SMEM_BYTES>>>(bias, out);
}

// round 5
// speedup vs baseline: 2.3098x; 2.0640x over previous
#include <cuda_runtime.h>
#include <cstdint>

#define W_DIM 81920
#define N_DIM 4
#define C_DIM 64
#define O_DIM 64
#define K_DIM 10
#define TILE_W 128
#define TILES_PER_N (W_DIM / TILE_W)            // 640
#define NTILES      (N_DIM * TILES_PER_N)       // 2560
#define TBL_ELEMS   (W_DIM * K_DIM)             // 819200
#define PHASES 10                               // one per k
#define STEPS  16                               // j4 steps per phase (64 c / 4)
#define GP 17                                   // gather pitch (float4 units) 16+1
#define WP 65                                   // weight pitch (float4 units) 64+1
#define GBUF (TILE_W * GP)                      // 2176 f4
#define WBUF (STEPS * WP)                       // 1040 f4
#define BUF_F4 (GBUF + WBUF)                    // 3216 f4 = 51456 B
#define SMEM_BYTES (2 * BUF_F4 * 16 + TILE_W * K_DIM * 4)   // 108032 B

// Static device scratch (no runtime allocation)
__device__ float g_xT[(size_t)N_DIM * W_DIM * C_DIM];  // input transposed [N,W,C]
__device__ float g_w4[O_DIM * C_DIM * K_DIM];          // weight, phase-major f4 layout
__device__ int   g_idx[TBL_ELEMS];                     // canonical int32 gather table
__device__ int   g_is_i32;

// ---------------------------------------------------------------------------
// conv_table dtype detection (reference says int64, JAX x64-off gives int32).
// Genuine int64 < 2^31 => every odd 32-bit word is 0. Probe first 512 B.
// ---------------------------------------------------------------------------
__global__ void detect_kernel(const int* __restrict__ t32) {
    __shared__ int f;
    if (threadIdx.x == 0) f = 0;
    __syncthreads();
    if (t32[2 * threadIdx.x + 1] != 0) atomicOr(&f, 1);
    __syncthreads();
    if (threadIdx.x == 0) g_is_i32 = f;
}

__global__ void convert_kernel(const int* __restrict__ t32) {
    int i = blockIdx.x * 256 + threadIdx.x;
    if (i < TBL_ELEMS)
        g_idx[i] = g_is_i32 ? t32[i] : t32[2 * i];
}

// ---------------------------------------------------------------------------
// input [N,C,W] -> g_xT [N,W,C]
// ---------------------------------------------------------------------------
__global__ void transpose_kernel(const float* __restrict__ in) {
    __shared__ float t[32][33];
    int n  = blockIdx.z;
    int c0 = blockIdx.y << 5;
    int w0 = blockIdx.x << 5;
    int tx = threadIdx.x, ty = threadIdx.y;

    const size_t inb = ((size_t)n * C_DIM + c0) * W_DIM + w0;
#pragma unroll
    for (int i = 0; i < 32; i += 8)
        t[ty + i][tx] = in[inb + (size_t)(ty + i) * W_DIM + tx];
    __syncthreads();
    const size_t ob = ((size_t)n * W_DIM + w0) * C_DIM + c0;
#pragma unroll
    for (int i = 0; i < 32; i += 8)
        g_xT[ob + (size_t)(ty + i) * C_DIM + tx] = t[tx][ty + i];
}

// ---------------------------------------------------------------------------
// weight [O,C,K,1] -> g_w4: f4 chunk index (k*16 + c/4)*64 + o, component c&3.
// Each f4 = (w[o][4cq][k], w[o][4cq+1][k], w[o][4cq+2][k], w[o][4cq+3][k]).
// ---------------------------------------------------------------------------
__global__ void wprep_kernel(const float* __restrict__ w) {
    int i = blockIdx.x * 256 + threadIdx.x;
    if (i < O_DIM * C_DIM * K_DIM) {
        int o = i / (C_DIM * K_DIM);
        int r = i - o * (C_DIM * K_DIM);
        int c = r / K_DIM;
        int k = r - c * K_DIM;
        g_w4[(((k * 16) + (c >> 2)) * O_DIM + o) * 4 + (c & 3)] =
            w[i];
    }
}

// ---------------------------------------------------------------------------
// Main kernel: persistent, tile = 128 w x 64 o. 10 k-phases, double-buffered
// operand streaming (gather + weight slice), 8w x 4o register tile per thread,
// f32x2 packed FMA. 256 threads: wq = tid&15 (w mod 16), og = tid>>4 (o-quad).
// ---------------------------------------------------------------------------
__global__ void __launch_bounds__(256, 1)
conv_kernel(const float* __restrict__ bias,
            float* __restrict__ out) {
    extern __shared__ float4 smem4[];
    float4* buf0  = smem4;
    float4* buf1  = smem4 + BUF_F4;
    int*    s_idx = (int*)(smem4 + 2 * BUF_F4);    // [128][10]

    const int tid = threadIdx.x;
    const int wq  = tid & 15;
    const int og  = tid >> 4;                       // 0..15, o = og*4 .. og*4+3

    float b[4];
#pragma unroll
    for (int r = 0; r < 4; ++r) b[r] = bias[og * 4 + r];

    for (int t = blockIdx.x; t < NTILES; t += gridDim.x) {
        const int n  = t / TILES_PER_N;
        const int w0 = (t - n * TILES_PER_N) * TILE_W;
        const float* xTn = g_xT + (size_t)n * W_DIM * C_DIM;

        // ---- per-tile index preload: 1280 ints ----
#pragma unroll
        for (int i = 0; i < 5; ++i)
            s_idx[tid + 256 * i] = g_idx[w0 * K_DIM + tid + 256 * i];
        __syncthreads();

        float4 gs[8], ws[4];

        // ---- load a phase into staging registers ----
        auto load_phase = [&](int p) {
#pragma unroll
            for (int c = 0; c < 8; ++c) {
                int lin = tid + 256 * c;           // 0..2047
                int row = lin >> 4;                // 0..127
                int c4  = lin & 15;
                gs[c] = *reinterpret_cast<const float4*>(
                    xTn + (size_t)s_idx[row * K_DIM + p] * C_DIM + c4 * 4);
            }
            const float4* w4 = reinterpret_cast<const float4*>(g_w4) + p * STEPS * O_DIM;
#pragma unroll
            for (int i = 0; i < 4; ++i)
                ws[i] = w4[tid + 256 * i];         // cq = lin>>6, o = lin&63
        };
        auto sts_phase = [&](float4* b4) {
#pragma unroll
            for (int c = 0; c < 8; ++c) {
                int lin = tid + 256 * c;
                int row = lin >> 4;
                int c4  = lin & 15;
                b4[row * GP + c4] = gs[c];
            }
#pragma unroll
            for (int i = 0; i < 4; ++i) {
                int lin = tid + 256 * i;
                int cq  = lin >> 6;
                int o   = lin & 63;
                b4[GBUF + cq * WP + o] = ws[i];
            }
        };

        // ---- prologue: phase 0 ----
        load_phase(0);
        sts_phase(buf0);
        __syncthreads();

        unsigned long long acc[8][4];
#pragma unroll
        for (int i = 0; i < 8; ++i)
#pragma unroll
            for (int r = 0; r < 4; ++r) acc[i][r] = 0ull;

        // ---- phase loop ----
        for (int p = 0; p < PHASES; ++p) {
            const float4* cb = (p & 1) ? buf1 : buf0;
            if (p < PHASES - 1) load_phase(p + 1);

#pragma unroll
            for (int cq = 0; cq < STEPS; ++cq) {
                ulonglong2 g[8], wt[4];
#pragma unroll
                for (int i = 0; i < 8; ++i)
                    g[i] = *reinterpret_cast<const ulonglong2*>(cb + (wq + 16 * i) * GP + cq);
#pragma unroll
                for (int r = 0; r < 4; ++r)
                    wt[r] = *reinterpret_cast<const ulonglong2*>(cb + GBUF + cq * WP + og * 4 + r);
#pragma unroll
                for (int i = 0; i < 8; ++i)
#pragma unroll
                    for (int r = 0; r < 4; ++r) {
                        asm("fma.rn.f32x2 %0, %1, %2, %0;"
                            : "+l"(acc[i][r]) : "l"(g[i].x), "l"(wt[r].x));
                        asm("fma.rn.f32x2 %0, %1, %2, %0;"
                            : "+l"(acc[i][r]) : "l"(g[i].y), "l"(wt[r].y));
                    }
            }

            if (p < PHASES - 1) sts_phase((p & 1) ? buf0 : buf1);
            __syncthreads();
        }

        // ---- epilogue: reduce halves, bias, relu, store ----
#pragma unroll
        for (int r = 0; r < 4; ++r) {
            const size_t ob = ((size_t)n * O_DIM + og * 4 + r) * W_DIM + w0;
#pragma unroll
            for (int i = 0; i < 8; ++i) {
                unsigned long long v = acc[i][r];
                float s = __uint_as_float((unsigned)v) +
                          __uint_as_float((unsigned)(v >> 32));
                out[ob + wq + 16 * i] = fmaxf(s + b[r], 0.0f);
            }
        }
        // s_idx overwrite for next tile is guarded by the phase-9 __syncthreads()
    }
}

// ---------------------------------------------------------------------------
extern "C" void kernel_launch(void* const* d_in, const int* in_sizes, int n_in,
                              void* d_out, int out_size) {
    const float* input  = (const float*)d_in[0];
    const int*   tbl32  = (const int*)d_in[1];
    const float* weight = (const float*)d_in[2];
    const float* bias   = (const float*)d_in[3];
    float*       out    = (float*)d_out;

    cudaFuncSetAttribute(conv_kernel,
                         cudaFuncAttributeMaxDynamicSharedMemorySize, SMEM_BYTES);

    int dev = 0;
    cudaGetDevice(&dev);
    int nsm = 148;
    cudaDeviceGetAttribute(&nsm, cudaDevAttrMultiProcessorCount, dev);

    detect_kernel<<<1, 64>>>(tbl32);
    convert_kernel<<<(TBL_ELEMS + 255) / 256, 256>>>(tbl32);
    transpose_kernel<<<dim3(W_DIM / 32, C_DIM / 32, N_DIM), dim3(32, 8)>>>(input);
    wprep_kernel<<<(O_DIM * C_DIM * K_DIM + 255) / 256, 256>>>(weight);
    conv_kernel<<<nsm, 256, SMEM_BYTES>>>(bias, out);
}